// round 1
// baseline (speedup 1.0000x reference)
#include <cuda_runtime.h>
#include <cstdint>
#include <cstddef>

// ---------------------------------------------------------------------------
// GATv2 x3 layers.  Dims: 4 -> 128 -> 512 -> 1028, H=32 heads, head-mean.
// Strategy:
//   per layer: xl = h@Wl+bl, xr = h@Wr+br   (SIMT 128x128x8 fp32 GEMM)
//   CSR by destination (built on device each call), then per (dst, head)
//   block does ONLINE softmax over in-edges: single read of xl[src] per edge.
//   Head mean via atomicAdd (scaled 1/H), then bias + leaky_relu epilogue.
// ---------------------------------------------------------------------------

#define MAX_N 10000
#define MAX_E 160000
#define MAX_EL (MAX_E + MAX_N)

// scratch (allocation-free rule: __device__ globals)
__device__ float g_xl[328960000];          // 10000 * 32 * 1028
__device__ float g_xr[328960000];
__device__ float g_h1[MAX_N * 128];
__device__ float g_h2[MAX_N * 512];
__device__ int   g_deg[MAX_N];
__device__ int   g_rowptr[MAX_N + 1];
__device__ int   g_cursor[MAX_N];
__device__ int   g_col[MAX_EL];

// ---------------------------------------------------------------------------
// CSR construction
// ---------------------------------------------------------------------------
__global__ void init_deg_k(int* deg, int n) {
    int i = blockIdx.x * blockDim.x + threadIdx.x;
    if (i < n) deg[i] = 1;  // self loop
}

__global__ void count_deg_k(const int* __restrict__ ei, int* deg, int E) {
    int e = blockIdx.x * blockDim.x + threadIdx.x;
    if (e < E) atomicAdd(&deg[ei[E + e]], 1);
}

__global__ void scan_rowptr_k(const int* __restrict__ deg, int* rowptr, int n) {
    __shared__ int sm[1024];
    __shared__ int carry;
    int tid = threadIdx.x;
    if (tid == 0) { carry = 0; rowptr[0] = 0; }
    __syncthreads();
    for (int base = 0; base < n; base += 1024) {
        int i = base + tid;
        int v = (i < n) ? deg[i] : 0;
        sm[tid] = v;
        __syncthreads();
        for (int off = 1; off < 1024; off <<= 1) {
            int t = (tid >= off) ? sm[tid - off] : 0;
            __syncthreads();
            sm[tid] += t;
            __syncthreads();
        }
        if (i < n) rowptr[i + 1] = carry + sm[tid];
        __syncthreads();
        if (tid == 0) carry += sm[1023];
        __syncthreads();
    }
}

__global__ void copy_cursor_k(const int* __restrict__ rowptr, int* cursor, int n) {
    int i = blockIdx.x * blockDim.x + threadIdx.x;
    if (i < n) cursor[i] = rowptr[i];
}

__global__ void scatter_edges_k(const int* __restrict__ ei, int* cursor,
                                int* colv, int E) {
    int e = blockIdx.x * blockDim.x + threadIdx.x;
    if (e < E) {
        int s = ei[e];
        int d = ei[E + e];
        int pos = atomicAdd(&cursor[d], 1);
        colv[pos] = s;
    }
}

__global__ void scatter_loops_k(int* cursor, int* colv, int n) {
    int i = blockIdx.x * blockDim.x + threadIdx.x;
    if (i < n) {
        int pos = atomicAdd(&cursor[i], 1);
        colv[pos] = i;
    }
}

// ---------------------------------------------------------------------------
// fp32 GEMM: C[M,Ncols] = A[M,K] @ B[K,Ncols] + bias[Ncols]
// 128x128 tile, BK=8, 256 threads, 8x8 per thread.  Ncols % 128 == 0, K % 4 == 0.
// ---------------------------------------------------------------------------
__global__ __launch_bounds__(256) void sgemm_bias_k(
    const float* __restrict__ A, const float* __restrict__ B,
    const float* __restrict__ bias, float* __restrict__ Cmat,
    int M, int K, int Ncols)
{
    __shared__ float As[8][132];
    __shared__ float Bs[8][132];
    int tid = threadIdx.x;
    int m0 = blockIdx.y * 128;
    int n0 = blockIdx.x * 128;
    int tr = (tid / 16) * 8;
    int tc = (tid % 16) * 8;

    int ar  = tid >> 1;         // 0..127 (A row within tile)
    int akq = (tid & 1) * 4;    // k sub-offset (0 or 4)
    int bk  = tid >> 5;         // 0..7
    int bc  = (tid & 31) * 4;   // 0..124

    float acc[8][8];
#pragma unroll
    for (int i = 0; i < 8; i++)
#pragma unroll
        for (int j = 0; j < 8; j++) acc[i][j] = 0.f;

    for (int k0 = 0; k0 < K; k0 += 8) {
        float4 av = make_float4(0.f, 0.f, 0.f, 0.f);
        if (m0 + ar < M && k0 + akq < K)
            av = *reinterpret_cast<const float4*>(&A[(size_t)(m0 + ar) * K + k0 + akq]);
        As[akq + 0][ar] = av.x;
        As[akq + 1][ar] = av.y;
        As[akq + 2][ar] = av.z;
        As[akq + 3][ar] = av.w;

        float4 bv = make_float4(0.f, 0.f, 0.f, 0.f);
        if (k0 + bk < K)
            bv = *reinterpret_cast<const float4*>(&B[(size_t)(k0 + bk) * Ncols + n0 + bc]);
        *reinterpret_cast<float4*>(&Bs[bk][bc]) = bv;
        __syncthreads();

#pragma unroll
        for (int kk = 0; kk < 8; kk++) {
            float a[8], b[8];
#pragma unroll
            for (int i = 0; i < 8; i++) a[i] = As[kk][tr + i];
#pragma unroll
            for (int j = 0; j < 8; j++) b[j] = Bs[kk][tc + j];
#pragma unroll
            for (int i = 0; i < 8; i++)
#pragma unroll
                for (int j = 0; j < 8; j++)
                    acc[i][j] += a[i] * b[j];
        }
        __syncthreads();
    }

#pragma unroll
    for (int i = 0; i < 8; i++) {
        int m = m0 + tr + i;
        if (m < M) {
#pragma unroll
            for (int j = 0; j < 8; j++) {
                int n = n0 + tc + j;
                Cmat[(size_t)m * Ncols + n] = acc[i][j] + bias[n];
            }
        }
    }
}

// ---------------------------------------------------------------------------
// Edge attention with online softmax.  Block = (dst, head), 128 threads.
// NCH = ceil(C / 128) channel chunks per thread.
// ---------------------------------------------------------------------------
template <int NCH>
__global__ __launch_bounds__(128) void gat_edge_k(
    const float* __restrict__ xl, const float* __restrict__ xr,
    const float* __restrict__ att, const int* __restrict__ rowptr,
    const int* __restrict__ colv, float* __restrict__ out,
    int C, float invH)
{
    const int TPB = 128;
    int dst = blockIdx.x;
    int h = blockIdx.y;
    int H = gridDim.y;
    int tid = threadIdx.x;
    __shared__ float ws[4];

    size_t base_d = ((size_t)dst * H + h) * C;

    float a[NCH], xd[NCH], acc[NCH];
#pragma unroll
    for (int j = 0; j < NCH; j++) {
        int c = tid + j * TPB;
        bool ok = c < C;
        a[j]   = ok ? att[(size_t)h * C + c] : 0.f;
        xd[j]  = ok ? xr[base_d + c] : 0.f;
        acc[j] = 0.f;
    }

    float m = -3.4e38f, l = 0.f;
    int e0 = rowptr[dst], e1 = rowptr[dst + 1];
    for (int e = e0; e < e1; e++) {
        int s = colv[e];
        size_t base_s = ((size_t)s * H + h) * C;
        float xs[NCH];
        float p = 0.f;
#pragma unroll
        for (int j = 0; j < NCH; j++) {
            int c = tid + j * TPB;
            float xv = (c < C) ? xl[base_s + c] : 0.f;
            xs[j] = xv;
            float v = xv + xd[j];
            v = v > 0.f ? v : 0.2f * v;
            p += a[j] * v;   // a[j]==0 out of range
        }
        // block reduce + broadcast
#pragma unroll
        for (int o = 16; o > 0; o >>= 1) p += __shfl_xor_sync(0xffffffffu, p, o);
        if ((tid & 31) == 0) ws[tid >> 5] = p;
        __syncthreads();
        float ev = ws[0] + ws[1] + ws[2] + ws[3];
        __syncthreads();

        float mn = fmaxf(m, ev);
        float sc = __expf(m - mn);    // first iter: exp(-inf)=0
        float w  = __expf(ev - mn);
#pragma unroll
        for (int j = 0; j < NCH; j++) acc[j] = acc[j] * sc + w * xs[j];
        l = l * sc + w;
        m = mn;
    }

    float inv = invH / l;   // degree >= 1 (self loop), l > 0
#pragma unroll
    for (int j = 0; j < NCH; j++) {
        int c = tid + j * TPB;
        if (c < C) atomicAdd(&out[(size_t)dst * C + c], acc[j] * inv);
    }
}

// ---------------------------------------------------------------------------
// utility kernels
// ---------------------------------------------------------------------------
__global__ void zero_f_k(float* p, size_t n) {
    size_t i = (size_t)blockIdx.x * blockDim.x + threadIdx.x;
    if (i < n) p[i] = 0.f;
}

__global__ void bias_act_k(float* h, const float* __restrict__ bias,
                           int total, int C, float slope, int do_act) {
    int i = blockIdx.x * blockDim.x + threadIdx.x;
    if (i < total) {
        int c = i % C;
        float v = h[i] + bias[c];
        if (do_act) v = v > 0.f ? v : slope * v;
        h[i] = v;
    }
}

// ---------------------------------------------------------------------------
// host orchestration
// ---------------------------------------------------------------------------
static void run_gemm(const float* A, const float* B, const float* bias, float* C,
                     int M, int K, int Ncols) {
    dim3 grid(Ncols / 128, (M + 127) / 128);
    sgemm_bias_k<<<grid, 256>>>(A, B, bias, C, M, K, Ncols);
}

static void run_layer(const float* hin, int fi, int fo,
                      const float* Wl, const float* bl,
                      const float* Wr, const float* br,
                      const float* att, const float* bias,
                      float* xl, float* xr,
                      const int* rowptr, const int* colv,
                      float* hout, int N, int H, bool act) {
    int Ncols = H * fo;
    run_gemm(hin, Wl, bl, xl, N, fi, Ncols);
    run_gemm(hin, Wr, br, xr, N, fi, Ncols);

    size_t outn = (size_t)N * fo;
    zero_f_k<<<(unsigned)((outn + 255) / 256), 256>>>(hout, outn);

    dim3 eg(N, H);
    float invH = 1.f / (float)H;
    if (fo <= 128)
        gat_edge_k<1><<<eg, 128>>>(xl, xr, att, rowptr, colv, hout, fo, invH);
    else if (fo <= 512)
        gat_edge_k<4><<<eg, 128>>>(xl, xr, att, rowptr, colv, hout, fo, invH);
    else
        gat_edge_k<9><<<eg, 128>>>(xl, xr, att, rowptr, colv, hout, fo, invH);

    bias_act_k<<<(unsigned)((outn + 255) / 256), 256>>>(
        hout, bias, (int)outn, fo, act ? 0.01f : 0.f, act ? 1 : 0);
}

extern "C" void kernel_launch(void* const* d_in, const int* in_sizes, int n_in,
                              void* d_out, int out_size) {
    const float* x  = (const float*)d_in[0];
    const int*   ei = (const int*)d_in[1];

    const float* W1l = (const float*)d_in[2];
    const float* b1l = (const float*)d_in[3];
    const float* W1r = (const float*)d_in[4];
    const float* b1r = (const float*)d_in[5];
    const float* at1 = (const float*)d_in[6];
    const float* bi1 = (const float*)d_in[7];
    const float* W2l = (const float*)d_in[8];
    const float* b2l = (const float*)d_in[9];
    const float* W2r = (const float*)d_in[10];
    const float* b2r = (const float*)d_in[11];
    const float* at2 = (const float*)d_in[12];
    const float* bi2 = (const float*)d_in[13];
    const float* W3l = (const float*)d_in[14];
    const float* b3l = (const float*)d_in[15];
    const float* W3r = (const float*)d_in[16];
    const float* b3r = (const float*)d_in[17];
    const float* at3 = (const float*)d_in[18];
    const float* bi3 = (const float*)d_in[19];

    int N = in_sizes[0] / 4;       // x is [N,4]
    int E = in_sizes[1] / 2;       // edge_index is [2,E]
    int f1 = in_sizes[7];          // bias1 -> 128
    int f2 = in_sizes[13];         // bias2 -> 512
    int f3 = in_sizes[19];         // bias3 -> 1028
    int H  = in_sizes[3] / f1;     // 32

    float *xl, *xr, *h1, *h2;
    int *deg, *rowptr, *cursor, *colv;
    cudaGetSymbolAddress((void**)&xl, g_xl);
    cudaGetSymbolAddress((void**)&xr, g_xr);
    cudaGetSymbolAddress((void**)&h1, g_h1);
    cudaGetSymbolAddress((void**)&h2, g_h2);
    cudaGetSymbolAddress((void**)&deg, g_deg);
    cudaGetSymbolAddress((void**)&rowptr, g_rowptr);
    cudaGetSymbolAddress((void**)&cursor, g_cursor);
    cudaGetSymbolAddress((void**)&colv, g_col);

    // --- CSR build (by destination) ---
    init_deg_k<<<(N + 255) / 256, 256>>>(deg, N);
    count_deg_k<<<(E + 255) / 256, 256>>>(ei, deg, E);
    scan_rowptr_k<<<1, 1024>>>(deg, rowptr, N);
    copy_cursor_k<<<(N + 255) / 256, 256>>>(rowptr, cursor, N);
    scatter_edges_k<<<(E + 255) / 256, 256>>>(ei, cursor, colv, E);
    scatter_loops_k<<<(N + 255) / 256, 256>>>(cursor, colv, N);

    // --- 3 GATv2 layers ---
    run_layer(x,  4,  f1, W1l, b1l, W1r, b1r, at1, bi1, xl, xr, rowptr, colv, h1, N, H, true);
    run_layer(h1, f1, f2, W2l, b2l, W2r, b2r, at2, bi2, xl, xr, rowptr, colv, h2, N, H, true);
    run_layer(h2, f2, f3, W3l, b3l, W3r, b3r, at3, bi3, xl, xr, rowptr, colv,
              (float*)d_out, N, H, false);
}

// round 3
// speedup vs baseline: 2.1700x; 2.1700x over previous
#include <cuda_runtime.h>
#include <cstdint>
#include <cstddef>

// ---------------------------------------------------------------------------
// GATv2 x3 layers.  Dims: 4 -> 128 -> 512 -> 1028, H=32 heads, head-mean.
//   GEMMs on mma.sync.m16n8k8 tf32 (sm_103 baseline tensor path; tcgen05
//   is unavailable: harness compiles for sm_103 without the 'a' suffix).
//   128x128 CTA tile, 4 warps x (64x64), BK=32, cp.async double buffer.
//   Edge phase: CSR-by-dst online softmax (unchanged from R1).
// ---------------------------------------------------------------------------

#define MAX_N 10000
#define MAX_E 160000
#define MAX_EL (MAX_E + MAX_N)

// scratch (allocation-free rule: __device__ globals)
__device__ float g_xl[328960000];          // 10000 * 32 * 1028
__device__ float g_xr[328960000];
__device__ float g_h1[MAX_N * 128];
__device__ float g_h2[MAX_N * 512];
__device__ int   g_deg[MAX_N];
__device__ int   g_rowptr[MAX_N + 1];
__device__ int   g_cursor[MAX_N];
__device__ int   g_col[MAX_EL];

// ---------------------------------------------------------------------------
// mma.sync tf32 GEMM
// ---------------------------------------------------------------------------
#define AS_STRIDE 36   // floats per A smem row  (128 rows)
#define BS_STRIDE 136  // floats per B smem row  (32 rows)
#define AS_BYTES (128 * AS_STRIDE * 4)   // 18432
#define BS_BYTES (32 * BS_STRIDE * 4)    // 17408
#define GEMM_SMEM (2 * (AS_BYTES + BS_BYTES))  // 71680

__device__ __forceinline__ void cp16(uint32_t dst, const void* src, int bytes) {
    asm volatile("cp.async.cg.shared.global [%0], [%1], 16, %2;"
                 :: "r"(dst), "l"(src), "r"(bytes) : "memory");
}
__device__ __forceinline__ void cp_commit() {
    asm volatile("cp.async.commit_group;" ::: "memory");
}
template <int N>
__device__ __forceinline__ void cp_wait() {
    asm volatile("cp.async.wait_group %0;" :: "n"(N) : "memory");
}
__device__ __forceinline__ uint32_t smem_u32(const void* p) {
    uint32_t a;
    asm("{ .reg .u64 t; cvta.to.shared.u64 t, %1; cvt.u32.u64 %0, t; }"
        : "=r"(a) : "l"(p));
    return a;
}
__device__ __forceinline__ uint32_t f2tf32(float x) {
    uint32_t u;
    asm("cvt.rna.tf32.f32 %0, %1;" : "=r"(u) : "f"(x));
    return u;
}
__device__ __forceinline__ void mma_tf32(float& c0, float& c1, float& c2, float& c3,
                                         uint32_t a0, uint32_t a1, uint32_t a2, uint32_t a3,
                                         uint32_t b0, uint32_t b1) {
    asm volatile(
        "mma.sync.aligned.m16n8k8.row.col.f32.tf32.tf32.f32 "
        "{%0,%1,%2,%3}, {%4,%5,%6,%7}, {%8,%9}, {%0,%1,%2,%3};"
        : "+f"(c0), "+f"(c1), "+f"(c2), "+f"(c3)
        : "r"(a0), "r"(a1), "r"(a2), "r"(a3), "r"(b0), "r"(b1));
}

// C[M,Ncols] = A[M,K] @ B[K,Ncols] + bias.   Ncols % 128 == 0, K % 4 == 0.
__global__ __launch_bounds__(128, 2) void gemm_mma_k(
    const float* __restrict__ A, const float* __restrict__ B,
    const float* __restrict__ bias, float* __restrict__ Cmat,
    int M, int K, int Ncols)
{
    extern __shared__ __align__(16) float dyn[];
    float* sA[2] = { dyn, dyn + AS_BYTES / 4 };
    float* sB[2] = { dyn + 2 * AS_BYTES / 4, dyn + 2 * AS_BYTES / 4 + BS_BYTES / 4 };

    const int tid = threadIdx.x;
    const int wid = tid >> 5;
    const int lane = tid & 31;
    const int gid = lane >> 2;   // 0..7
    const int tig = lane & 3;    // 0..3
    const int m0 = blockIdx.x * 128;
    const int n0 = blockIdx.y * 128;
    const int warpM = (wid >> 1) * 64;
    const int warpN = (wid & 1) * 64;

    const int nChunks = (K + 31) / 32;

    // ---- async stage of one k-chunk into buffer b ----
    auto stage = [&](int chunk, int b) {
        const int k0 = chunk * 32;
        uint32_t sAu = smem_u32(sA[b]);
        uint32_t sBu = smem_u32(sB[b]);
#pragma unroll
        for (int it = 0; it < 8; it++) {           // A: 1024 float4 / 128 thr
            int idx = tid + it * 128;
            int row = idx >> 3;
            int kq = (idx & 7) * 4;
            bool ok = (m0 + row < M) && (k0 + kq < K);
            const float* src = ok ? &A[(size_t)(m0 + row) * K + k0 + kq] : A;
            cp16(sAu + (row * AS_STRIDE + kq) * 4, src, ok ? 16 : 0);
        }
#pragma unroll
        for (int it = 0; it < 8; it++) {           // B: 1024 float4 / 128 thr
            int idx = tid + it * 128;
            int k = idx >> 5;
            int nq = (idx & 31) * 4;
            bool ok = (k0 + k < K);
            const float* src = ok ? &B[(size_t)(k0 + k) * Ncols + n0 + nq] : B;
            cp16(sBu + (k * BS_STRIDE + nq) * 4, src, ok ? 16 : 0);
        }
        cp_commit();
    };

    float acc[4][8][4];
#pragma unroll
    for (int i = 0; i < 4; i++)
#pragma unroll
        for (int j = 0; j < 8; j++)
#pragma unroll
            for (int q = 0; q < 4; q++) acc[i][j][q] = 0.f;

    stage(0, 0);

    for (int t = 0; t < nChunks; t++) {
        if (t + 1 < nChunks) { stage(t + 1, (t + 1) & 1); cp_wait<1>(); }
        else                 { cp_wait<0>(); }
        __syncthreads();

        const float* cA = sA[t & 1];
        const float* cB = sB[t & 1];
#pragma unroll
        for (int kk = 0; kk < 32; kk += 8) {
            uint32_t af[4][4];
#pragma unroll
            for (int i = 0; i < 4; i++) {
                int r = warpM + i * 16 + gid;
                af[i][0] = f2tf32(cA[(r)     * AS_STRIDE + kk + tig]);
                af[i][1] = f2tf32(cA[(r + 8) * AS_STRIDE + kk + tig]);
                af[i][2] = f2tf32(cA[(r)     * AS_STRIDE + kk + tig + 4]);
                af[i][3] = f2tf32(cA[(r + 8) * AS_STRIDE + kk + tig + 4]);
            }
            uint32_t bf[8][2];
#pragma unroll
            for (int j = 0; j < 8; j++) {
                int n = warpN + j * 8 + gid;
                bf[j][0] = f2tf32(cB[(kk + tig)     * BS_STRIDE + n]);
                bf[j][1] = f2tf32(cB[(kk + tig + 4) * BS_STRIDE + n]);
            }
#pragma unroll
            for (int i = 0; i < 4; i++)
#pragma unroll
                for (int j = 0; j < 8; j++)
                    mma_tf32(acc[i][j][0], acc[i][j][1], acc[i][j][2], acc[i][j][3],
                             af[i][0], af[i][1], af[i][2], af[i][3],
                             bf[j][0], bf[j][1]);
        }
        __syncthreads();
    }

    // epilogue: c0/c1 -> (row, 2*tig), (row, 2*tig+1); c2/c3 -> row+8
#pragma unroll
    for (int i = 0; i < 4; i++) {
        int r0 = m0 + warpM + i * 16 + gid;
#pragma unroll
        for (int j = 0; j < 8; j++) {
            int c = n0 + warpN + j * 8 + tig * 2;
            float b0 = __ldg(&bias[c]);
            float b1 = __ldg(&bias[c + 1]);
            if (r0 < M) {
                float2 v = make_float2(acc[i][j][0] + b0, acc[i][j][1] + b1);
                *reinterpret_cast<float2*>(&Cmat[(size_t)r0 * Ncols + c]) = v;
            }
            if (r0 + 8 < M) {
                float2 v = make_float2(acc[i][j][2] + b0, acc[i][j][3] + b1);
                *reinterpret_cast<float2*>(&Cmat[(size_t)(r0 + 8) * Ncols + c]) = v;
            }
        }
    }
}

// ---------------------------------------------------------------------------
// CSR construction
// ---------------------------------------------------------------------------
__global__ void init_deg_k(int* deg, int n) {
    int i = blockIdx.x * blockDim.x + threadIdx.x;
    if (i < n) deg[i] = 1;
}
__global__ void count_deg_k(const int* __restrict__ ei, int* deg, int E) {
    int e = blockIdx.x * blockDim.x + threadIdx.x;
    if (e < E) atomicAdd(&deg[ei[E + e]], 1);
}
__global__ void scan_rowptr_k(const int* __restrict__ deg, int* rowptr, int n) {
    __shared__ int sm[1024];
    __shared__ int carry;
    int tid = threadIdx.x;
    if (tid == 0) { carry = 0; rowptr[0] = 0; }
    __syncthreads();
    for (int base = 0; base < n; base += 1024) {
        int i = base + tid;
        int v = (i < n) ? deg[i] : 0;
        sm[tid] = v;
        __syncthreads();
        for (int off = 1; off < 1024; off <<= 1) {
            int t = (tid >= off) ? sm[tid - off] : 0;
            __syncthreads();
            sm[tid] += t;
            __syncthreads();
        }
        if (i < n) rowptr[i + 1] = carry + sm[tid];
        __syncthreads();
        if (tid == 0) carry += sm[1023];
        __syncthreads();
    }
}
__global__ void copy_cursor_k(const int* __restrict__ rowptr, int* cursor, int n) {
    int i = blockIdx.x * blockDim.x + threadIdx.x;
    if (i < n) cursor[i] = rowptr[i];
}
__global__ void scatter_edges_k(const int* __restrict__ ei, int* cursor,
                                int* colv, int E) {
    int e = blockIdx.x * blockDim.x + threadIdx.x;
    if (e < E) {
        int s = ei[e];
        int d = ei[E + e];
        int pos = atomicAdd(&cursor[d], 1);
        colv[pos] = s;
    }
}
__global__ void scatter_loops_k(int* cursor, int* colv, int n) {
    int i = blockIdx.x * blockDim.x + threadIdx.x;
    if (i < n) {
        int pos = atomicAdd(&cursor[i], 1);
        colv[pos] = i;
    }
}

// ---------------------------------------------------------------------------
// Edge attention with online softmax.  Block = (dst, head), 128 threads.
// ---------------------------------------------------------------------------
template <int NCH>
__global__ __launch_bounds__(128) void gat_edge_k(
    const float* __restrict__ xl, const float* __restrict__ xr,
    const float* __restrict__ att, const int* __restrict__ rowptr,
    const int* __restrict__ colv, float* __restrict__ out,
    int C, float invH)
{
    const int TPB = 128;
    int dst = blockIdx.x;
    int h = blockIdx.y;
    int H = gridDim.y;
    int tid = threadIdx.x;
    __shared__ float ws[4];

    size_t base_d = ((size_t)dst * H + h) * C;

    float a[NCH], xd[NCH], acc[NCH];
#pragma unroll
    for (int j = 0; j < NCH; j++) {
        int c = tid + j * TPB;
        bool ok = c < C;
        a[j]   = ok ? att[(size_t)h * C + c] : 0.f;
        xd[j]  = ok ? xr[base_d + c] : 0.f;
        acc[j] = 0.f;
    }

    float m = -3.4e38f, l = 0.f;
    int e0 = rowptr[dst], e1 = rowptr[dst + 1];
    for (int e = e0; e < e1; e++) {
        int s = colv[e];
        size_t base_s = ((size_t)s * H + h) * C;
        float xs[NCH];
        float p = 0.f;
#pragma unroll
        for (int j = 0; j < NCH; j++) {
            int c = tid + j * TPB;
            float xv = (c < C) ? xl[base_s + c] : 0.f;
            xs[j] = xv;
            float v = xv + xd[j];
            v = v > 0.f ? v : 0.2f * v;
            p += a[j] * v;
        }
#pragma unroll
        for (int o = 16; o > 0; o >>= 1) p += __shfl_xor_sync(0xffffffffu, p, o);
        if ((tid & 31) == 0) ws[tid >> 5] = p;
        __syncthreads();
        float ev = ws[0] + ws[1] + ws[2] + ws[3];
        __syncthreads();

        float mn = fmaxf(m, ev);
        float sc = __expf(m - mn);
        float w  = __expf(ev - mn);
#pragma unroll
        for (int j = 0; j < NCH; j++) acc[j] = acc[j] * sc + w * xs[j];
        l = l * sc + w;
        m = mn;
    }

    float inv = invH / l;
#pragma unroll
    for (int j = 0; j < NCH; j++) {
        int c = tid + j * TPB;
        if (c < C) atomicAdd(&out[(size_t)dst * C + c], acc[j] * inv);
    }
}

// ---------------------------------------------------------------------------
// utility kernels
// ---------------------------------------------------------------------------
__global__ void zero_f_k(float* p, size_t n) {
    size_t i = (size_t)blockIdx.x * blockDim.x + threadIdx.x;
    if (i < n) p[i] = 0.f;
}
__global__ void bias_act_k(float* h, const float* __restrict__ bias,
                           int total, int C, float slope, int do_act) {
    int i = blockIdx.x * blockDim.x + threadIdx.x;
    if (i < total) {
        int c = i % C;
        float v = h[i] + bias[c];
        if (do_act) v = v > 0.f ? v : slope * v;
        h[i] = v;
    }
}

// ---------------------------------------------------------------------------
// host orchestration
// ---------------------------------------------------------------------------
static void run_gemm(const float* A, const float* B, const float* bias, float* C,
                     int M, int K, int Ncols) {
    dim3 grid((M + 127) / 128, Ncols / 128);   // x = M tiles fastest -> A stays in L2
    gemm_mma_k<<<grid, 128, GEMM_SMEM>>>(A, B, bias, C, M, K, Ncols);
}

static void run_layer(const float* hin, int fi, int fo,
                      const float* Wl, const float* bl,
                      const float* Wr, const float* br,
                      const float* att, const float* bias,
                      float* xl, float* xr,
                      const int* rowptr, const int* colv,
                      float* hout, int N, int H, bool act) {
    int Ncols = H * fo;
    run_gemm(hin, Wl, bl, xl, N, fi, Ncols);
    run_gemm(hin, Wr, br, xr, N, fi, Ncols);

    size_t outn = (size_t)N * fo;
    zero_f_k<<<(unsigned)((outn + 255) / 256), 256>>>(hout, outn);

    dim3 eg(N, H);
    float invH = 1.f / (float)H;
    if (fo <= 128)
        gat_edge_k<1><<<eg, 128>>>(xl, xr, att, rowptr, colv, hout, fo, invH);
    else if (fo <= 512)
        gat_edge_k<4><<<eg, 128>>>(xl, xr, att, rowptr, colv, hout, fo, invH);
    else
        gat_edge_k<9><<<eg, 128>>>(xl, xr, att, rowptr, colv, hout, fo, invH);

    bias_act_k<<<(unsigned)((outn + 255) / 256), 256>>>(
        hout, bias, (int)outn, fo, act ? 0.01f : 0.f, act ? 1 : 0);
}

extern "C" void kernel_launch(void* const* d_in, const int* in_sizes, int n_in,
                              void* d_out, int out_size) {
    const float* x  = (const float*)d_in[0];
    const int*   ei = (const int*)d_in[1];

    const float* W1l = (const float*)d_in[2];
    const float* b1l = (const float*)d_in[3];
    const float* W1r = (const float*)d_in[4];
    const float* b1r = (const float*)d_in[5];
    const float* at1 = (const float*)d_in[6];
    const float* bi1 = (const float*)d_in[7];
    const float* W2l = (const float*)d_in[8];
    const float* b2l = (const float*)d_in[9];
    const float* W2r = (const float*)d_in[10];
    const float* b2r = (const float*)d_in[11];
    const float* at2 = (const float*)d_in[12];
    const float* bi2 = (const float*)d_in[13];
    const float* W3l = (const float*)d_in[14];
    const float* b3l = (const float*)d_in[15];
    const float* W3r = (const float*)d_in[16];
    const float* b3r = (const float*)d_in[17];
    const float* at3 = (const float*)d_in[18];
    const float* bi3 = (const float*)d_in[19];

    int N = in_sizes[0] / 4;
    int E = in_sizes[1] / 2;
    int f1 = in_sizes[7];
    int f2 = in_sizes[13];
    int f3 = in_sizes[19];
    int H  = in_sizes[3] / f1;

    cudaFuncSetAttribute(gemm_mma_k, cudaFuncAttributeMaxDynamicSharedMemorySize,
                         GEMM_SMEM);

    float *xl, *xr, *h1, *h2;
    int *deg, *rowptr, *cursor, *colv;
    cudaGetSymbolAddress((void**)&xl, g_xl);
    cudaGetSymbolAddress((void**)&xr, g_xr);
    cudaGetSymbolAddress((void**)&h1, g_h1);
    cudaGetSymbolAddress((void**)&h2, g_h2);
    cudaGetSymbolAddress((void**)&deg, g_deg);
    cudaGetSymbolAddress((void**)&rowptr, g_rowptr);
    cudaGetSymbolAddress((void**)&cursor, g_cursor);
    cudaGetSymbolAddress((void**)&colv, g_col);

    // --- CSR build (by destination) ---
    init_deg_k<<<(N + 255) / 256, 256>>>(deg, N);
    count_deg_k<<<(E + 255) / 256, 256>>>(ei, deg, E);
    scan_rowptr_k<<<1, 1024>>>(deg, rowptr, N);
    copy_cursor_k<<<(N + 255) / 256, 256>>>(rowptr, cursor, N);
    scatter_edges_k<<<(E + 255) / 256, 256>>>(ei, cursor, colv, E);
    scatter_loops_k<<<(N + 255) / 256, 256>>>(cursor, colv, N);

    // --- 3 GATv2 layers ---
    run_layer(x,  4,  f1, W1l, b1l, W1r, b1r, at1, bi1, xl, xr, rowptr, colv, h1, N, H, true);
    run_layer(h1, f1, f2, W2l, b2l, W2r, b2r, at2, bi2, xl, xr, rowptr, colv, h2, N, H, true);
    run_layer(h2, f2, f3, W3l, b3l, W3r, b3r, at3, bi3, xl, xr, rowptr, colv,
              (float*)d_out, N, H, false);
}